// round 13
// baseline (speedup 1.0000x reference)
#include <cuda_runtime.h>
#include <cuda_fp16.h>
#include <cstdint>

// ============================================================================
// BSpline via warp-level mma.sync (HMMA).
//   out[b,o] = sum_{i,c} basis(x[b,i])[c] * cp[i,c,o]
//   = GEMM: A (rows x 768) * B (768 x 64), k = i*12 + c.
// R13 = R11 (M32xN32 warp tile, M_TILE=128, 8 passes of K=96, 3 CTA/SM)
//   + restored depth-1 double-buffering of BOTH the A ldmatrix loads and the
//   B fragment LDGs (R11 serialized LDSM->MMA each kstep; that, not the tile
//   shape, caused its regression). L1 wavefronts/MMA drop 3 -> 2 vs R10.
// ============================================================================

#define DIMS 64
#define KSTEPS 48          // 768 / 16
#define NPASS 8
#define KS_PASS 6          // ksteps per pass
#define M_TILE 128
#define THREADS 256

#define A_PITCH_B 208      // bytes per A row per pass (odd x 16B)
#define SMEM_A_BYTES (M_TILE * A_PITCH_B)        // 26624
#define SMEM_TAB SMEM_A_BYTES
#define SMEM_TOTAL (SMEM_A_BYTES + 512)

// B fragments: [kstep][n][kq] -> uint2 {h(k0),h(k0+1) | h(k0+8),h(k0+9)}
// k0 = kstep*16 + kq*2, value = cp[k][n].
__device__ uint2 g_Bf[KSTEPS * 64 * 4];

static __device__ __forceinline__ uint32_t s2u(const void* p) {
    uint32_t a;
    asm("{ .reg .u64 t; cvta.to.shared.u64 t, %1; cvt.u32.u64 %0, t; }" : "=r"(a) : "l"(p));
    return a;
}

static __device__ __forceinline__ float4 ldg_cs_f4(const float* p) {
    float4 v;
    asm volatile("ld.global.cs.v4.f32 {%0,%1,%2,%3}, [%4];"
                 : "=f"(v.x), "=f"(v.y), "=f"(v.z), "=f"(v.w) : "l"(p));
    return v;
}

static __device__ __forceinline__ void stg_cs_f2(float* p, float a, float b) {
    asm volatile("st.global.cs.v2.f32 [%0], {%1,%2};" :: "l"(p), "f"(a), "f"(b) : "memory");
}

static __device__ __forceinline__ void ldsm_x4(uint32_t& r0, uint32_t& r1,
                                               uint32_t& r2, uint32_t& r3,
                                               uint32_t addr) {
    asm volatile("ldmatrix.sync.aligned.m8n8.x4.shared.b16 {%0,%1,%2,%3}, [%4];"
                 : "=r"(r0), "=r"(r1), "=r"(r2), "=r"(r3) : "r"(addr));
}

static __device__ __forceinline__ void mma16816(float& d0, float& d1, float& d2, float& d3,
                                                uint32_t a0, uint32_t a1, uint32_t a2, uint32_t a3,
                                                uint32_t b0, uint32_t b1) {
    asm("mma.sync.aligned.m16n8k16.row.col.f32.f16.f16.f32 "
        "{%0,%1,%2,%3}, {%4,%5,%6,%7}, {%8,%9}, {%0,%1,%2,%3};"
        : "+f"(d0), "+f"(d1), "+f"(d2), "+f"(d3)
        : "r"(a0), "r"(a1), "r"(a2), "r"(a3), "r"(b0), "r"(b1));
}

static __device__ __forceinline__ float knotv(int k) {
    int v = max(0, min(9, k - 3));
    return (float)v / 9.0f;
}

static __device__ __forceinline__ uint32_t packh2(float a, float b) {
    uint32_t r;
    asm("cvt.rn.f16x2.f32 %0, %2, %1;" : "=r"(r) : "f"(a), "f"(b));
    return r;
}

// ---------------------------------------------------------------------------
// Prep: cp fp32 (seen as [k][o], k = i*12+c) -> fragment-ordered fp16 g_Bf.
// ---------------------------------------------------------------------------
__global__ void bspline_prep_kernel(const float* __restrict__ cp) {
    int tid = blockIdx.x * blockDim.x + threadIdx.x;
    if (tid < KSTEPS * 64 * 4) {
        int kq = tid & 3;
        int n = (tid >> 2) & 63;
        int kstep = tid >> 8;
        int k0 = kstep * 16 + kq * 2;
        uint2 v;
        v.x = packh2(cp[(k0 + 0) * 64 + n], cp[(k0 + 1) * 64 + n]);
        v.y = packh2(cp[(k0 + 8) * 64 + n], cp[(k0 + 9) * 64 + n]);
        g_Bf[tid] = v;
    }
}

// ---------------------------------------------------------------------------
// Main kernel: one CTA = 128 rows, 8 warps = 4(M) x 2(N), warp tile M32xN32.
// K processed in 8 passes of 96 (i in [8p, 8p+8), ksteps [6p, 6p+6)).
// ---------------------------------------------------------------------------
__global__ __launch_bounds__(THREADS, 3)
void bspline_hmma_kernel(const float* __restrict__ x,
                         float* __restrict__ out,
                         int nrows)
{
    extern __shared__ char sm[];
    const uint32_t sb = s2u(sm);
    const int t = threadIdx.x;
    const int wid = t >> 5;
    const int lid = t & 31;
    const int row0 = blockIdx.x * M_TILE;

    // Per-span table: {T[j-2..j+3], i1,i2a,i2b,i3a,i3b,i3c}, j = s+3
    float* tab = (float*)(sm + SMEM_TAB);
    if (t < 9) {
        const int j = t + 3;
        float* e = tab + t * 12;
        e[0] = knotv(j - 2); e[1] = knotv(j - 1); e[2] = knotv(j);
        e[3] = knotv(j + 1); e[4] = knotv(j + 2); e[5] = knotv(j + 3);
        e[6]  = 1.0f / (e[3] - e[2]);
        e[7]  = 1.0f / (e[3] - e[1]);
        e[8]  = 1.0f / (e[4] - e[2]);
        e[9]  = 1.0f / (e[3] - e[0]);
        e[10] = 1.0f / (e[4] - e[1]);
        e[11] = 1.0f / (e[5] - e[2]);
    }

    // Warp-tile constants (stable across passes)
    const int mbase = (wid >> 1) * 32;      // 0,32,64,96
    const int nb    = wid & 1;              // N group -> nbase = nb*32
    const int lrow = (lid & 7) + ((lid >> 3) & 1) * 8;
    const int lcol = (lid >> 4) * 16;
    const uint32_t aAddr0 = sb + (uint32_t)(mbase + lrow) * A_PITCH_B + lcol;
    const uint32_t aAddr1 = aAddr0 + 16u * A_PITCH_B;
    const uint2* __restrict__ Bf = g_Bf;
    const int bLane = (nb * 32 + (lid >> 2)) * 4 + (lid & 3);

    float acc[2][4][4];
    #pragma unroll
    for (int mt = 0; mt < 2; mt++)
        #pragma unroll
        for (int nt = 0; nt < 4; nt++)
            #pragma unroll
            for (int q = 0; q < 4; q++) acc[mt][nt][q] = 0.0f;

    #pragma unroll
    for (int pass = 0; pass < NPASS; pass++) {
        __syncthreads();   // pass 0: after table init; later: A-tile WAR

        // ------------- Build phase: i in [8*pass, 8*pass+8) -------------
        // 128 rows x 2 i-quads = 256 tasks, 1 per thread.
        {
            const int r = t >> 1;               // row in tile
            const int iql = t & 1;              // local i-quad (0..1)
            const int row = min(row0 + r, nrows - 1);

            const float4 xv = ldg_cs_f4(x + (size_t)row * DIMS + (pass * 2 + iql) * 4);
            const uint32_t wbase = sb + (uint32_t)r * A_PITCH_B + (uint32_t)iql * 96u;

            #pragma unroll
            for (int u = 0; u < 4; u++) {
                float xc = (u == 0) ? xv.x : (u == 1) ? xv.y : (u == 2) ? xv.z : xv.w;
                xc = fminf(fmaxf(xc, 0.0f), 1.0f);

                const int s9 = min(8, (int)(xc * 9.0f));
                const float4* tb = (const float4*)(tab + s9 * 12);
                const float4 t0 = tb[0];
                const float4 t1 = tb[1];
                const float4 t2 = tb[2];

                const float l1 = xc - t0.z, r1 = t0.w - xc;
                const float l2 = xc - t0.y, r2 = t1.x - xc;
                const float l3 = xc - t0.x, r3 = t1.y - xc;

                float N0, N1, N2, N3, tmp, sv;
                tmp = t1.z;
                N0 = r1 * tmp; N1 = l1 * tmp;
                tmp = N0 * t1.w;
                N0 = r1 * tmp; sv = l2 * tmp;
                tmp = N1 * t2.x;
                N1 = fmaf(r2, tmp, sv); N2 = l1 * tmp;
                tmp = N0 * t2.y;
                N0 = r1 * tmp; sv = l3 * tmp;
                tmp = N1 * t2.z;
                N1 = fmaf(r2, tmp, sv); sv = l2 * tmp;
                tmp = N2 * t2.w;
                N2 = fmaf(r3, tmp, sv); N3 = l1 * tmp;

                const uint64_t w64 = (uint64_t)packh2(N0, N1)
                                   | ((uint64_t)packh2(N2, N3) << 32);
                const int sl = s9 >> 2;
                const int rs = (s9 & 3) * 16;
                const uint64_t lo = w64 << rs;
                const uint64_t hi = rs ? (w64 >> (64 - rs)) : 0ULL;

                const uint64_t a0 = (sl == 0) ? lo : 0ULL;
                const uint64_t a1 = (sl == 1) ? lo : ((sl == 0) ? hi : 0ULL);
                const uint64_t a2 = (sl == 2) ? lo : ((sl == 1) ? hi : 0ULL);

                const uint32_t w = wbase + (uint32_t)u * 24u;
                asm volatile("st.shared.u64 [%0], %1;" :: "r"(w),      "l"(a0) : "memory");
                asm volatile("st.shared.u64 [%0], %1;" :: "r"(w + 8),  "l"(a1) : "memory");
                asm volatile("st.shared.u64 [%0], %1;" :: "r"(w + 16), "l"(a2) : "memory");
            }
        }
        __syncthreads();

        // ------------- MMA phase: ksteps [6*pass, 6*pass+6) -------------
        uint32_t a[2][8];
        uint2 b[2][4];
        const int ksg0 = pass * KS_PASS;

        // prologue: stage ksl=0
        ldsm_x4(a[0][0], a[0][1], a[0][2], a[0][3], aAddr0);
        ldsm_x4(a[0][4], a[0][5], a[0][6], a[0][7], aAddr1);
        {
            const int bi = ksg0 * 256 + bLane;
            #pragma unroll
            for (int nt = 0; nt < 4; nt++) b[0][nt] = __ldg(Bf + bi + nt * 32);
        }

        #pragma unroll
        for (int ksl = 0; ksl < KS_PASS; ksl++) {
            const int cur = ksl & 1;
            const int nxt = cur ^ 1;
            if (ksl + 1 < KS_PASS) {
                ldsm_x4(a[nxt][0], a[nxt][1], a[nxt][2], a[nxt][3],
                        aAddr0 + (ksl + 1) * 32);
                ldsm_x4(a[nxt][4], a[nxt][5], a[nxt][6], a[nxt][7],
                        aAddr1 + (ksl + 1) * 32);
                const int bi = (ksg0 + ksl + 1) * 256 + bLane;
                #pragma unroll
                for (int nt = 0; nt < 4; nt++) b[nxt][nt] = __ldg(Bf + bi + nt * 32);
            }
            #pragma unroll
            for (int nt = 0; nt < 4; nt++) {
                mma16816(acc[0][nt][0], acc[0][nt][1], acc[0][nt][2], acc[0][nt][3],
                         a[cur][0], a[cur][1], a[cur][2], a[cur][3],
                         b[cur][nt].x, b[cur][nt].y);
                mma16816(acc[1][nt][0], acc[1][nt][1], acc[1][nt][2], acc[1][nt][3],
                         a[cur][4], a[cur][5], a[cur][6], a[cur][7],
                         b[cur][nt].x, b[cur][nt].y);
            }
        }
    }

    // ---------------- Epilogue: streaming float2 stores ----------------
    const int rquad = lid >> 2;
    const int npair = (lid & 3) * 2;
    #pragma unroll
    for (int mt = 0; mt < 2; mt++) {
        #pragma unroll
        for (int nt = 0; nt < 4; nt++) {
            const int col = nb * 32 + nt * 8 + npair;
            const int rA = row0 + mbase + mt * 16 + rquad;
            const int rB = rA + 8;
            if (rA < nrows)
                stg_cs_f2(out + (size_t)rA * DIMS + col, acc[mt][nt][0], acc[mt][nt][1]);
            if (rB < nrows)
                stg_cs_f2(out + (size_t)rB * DIMS + col, acc[mt][nt][2], acc[mt][nt][3]);
        }
    }
}

extern "C" void kernel_launch(void* const* d_in, const int* in_sizes, int n_in,
                              void* d_out, int out_size)
{
    const float* x  = (const float*)d_in[0];   // (65536, 64)
    const float* cp = (const float*)d_in[1];   // (64, 12, 64) == B[768][64]
    float* out = (float*)d_out;

    const int nrows = in_sizes[0] / DIMS;

    bspline_prep_kernel<<<(KSTEPS * 64 * 4 + 255) / 256, 256>>>(cp);

    cudaFuncSetAttribute(bspline_hmma_kernel,
                         cudaFuncAttributeMaxDynamicSharedMemorySize, SMEM_TOTAL);
    const int grid = (nrows + M_TILE - 1) / M_TILE;
    bspline_hmma_kernel<<<grid, THREADS, SMEM_TOTAL>>>(x, out, nrows);
}

// round 14
// speedup vs baseline: 1.1821x; 1.1821x over previous
#include <cuda_runtime.h>
#include <cuda_fp16.h>
#include <cstdint>

// ============================================================================
// BSpline via warp-level mma.sync (HMMA).
//   out[b,o] = sum_{i,c} basis(x[b,i])[c] * cp[i,c,o]
//   = GEMM: A (rows x 768) * B (768 x 64), k = i*12 + c.
// R14 = R12 (M16xN32, 4 k-passes, 4 CTA/SM, 32 warps/SM) +
//   (1) x staged to SMEM once with coalesced loads (kills 3 of 4 per-pass
//       DRAM latency exposures; build reads x via LDS),
//   (2) epilogue restaged through SMEM for coalesced STG.128 (wf 512->~260).
// ============================================================================

#define DIMS 64
#define KSTEPS 48          // 768 / 16
#define NPASS 4
#define KS_PASS 12         // ksteps per pass
#define M_TILE 64
#define THREADS 256

#define A_PITCH_B 400      // bytes per A row per pass (odd x 16B)
#define XS_PITCH_B 272     // bytes per x row (64 floats + 16B pad)
#define SMEM_A 0
#define SMEM_XS (M_TILE * A_PITCH_B)                 // 25600
#define SMEM_TAB (SMEM_XS + M_TILE * XS_PITCH_B)     // 43008
#define SMEM_TOTAL (SMEM_TAB + 512)                  // 43520

// B fragments: [kstep][n][kq] -> uint2 {h(k0),h(k0+1) | h(k0+8),h(k0+9)}
__device__ uint2 g_Bf[KSTEPS * 64 * 4];

static __device__ __forceinline__ uint32_t s2u(const void* p) {
    uint32_t a;
    asm("{ .reg .u64 t; cvta.to.shared.u64 t, %1; cvt.u32.u64 %0, t; }" : "=r"(a) : "l"(p));
    return a;
}

static __device__ __forceinline__ float4 ldg_cs_f4(const float* p) {
    float4 v;
    asm volatile("ld.global.cs.v4.f32 {%0,%1,%2,%3}, [%4];"
                 : "=f"(v.x), "=f"(v.y), "=f"(v.z), "=f"(v.w) : "l"(p));
    return v;
}

static __device__ __forceinline__ void stg_cs_f4(float* p, float4 v) {
    asm volatile("st.global.cs.v4.f32 [%0], {%1,%2,%3,%4};"
                 :: "l"(p), "f"(v.x), "f"(v.y), "f"(v.z), "f"(v.w) : "memory");
}

static __device__ __forceinline__ void ldsm_x4(uint32_t& r0, uint32_t& r1,
                                               uint32_t& r2, uint32_t& r3,
                                               uint32_t addr) {
    asm volatile("ldmatrix.sync.aligned.m8n8.x4.shared.b16 {%0,%1,%2,%3}, [%4];"
                 : "=r"(r0), "=r"(r1), "=r"(r2), "=r"(r3) : "r"(addr));
}

static __device__ __forceinline__ void mma16816(float& d0, float& d1, float& d2, float& d3,
                                                uint32_t a0, uint32_t a1, uint32_t a2, uint32_t a3,
                                                uint32_t b0, uint32_t b1) {
    asm("mma.sync.aligned.m16n8k16.row.col.f32.f16.f16.f32 "
        "{%0,%1,%2,%3}, {%4,%5,%6,%7}, {%8,%9}, {%0,%1,%2,%3};"
        : "+f"(d0), "+f"(d1), "+f"(d2), "+f"(d3)
        : "r"(a0), "r"(a1), "r"(a2), "r"(a3), "r"(b0), "r"(b1));
}

static __device__ __forceinline__ float knotv(int k) {
    int v = max(0, min(9, k - 3));
    return (float)v / 9.0f;
}

static __device__ __forceinline__ uint32_t packh2(float a, float b) {
    uint32_t r;
    asm("cvt.rn.f16x2.f32 %0, %2, %1;" : "=r"(r) : "f"(a), "f"(b));
    return r;
}

// ---------------------------------------------------------------------------
// Prep: cp fp32 (seen as [k][o], k = i*12+c) -> fragment-ordered fp16 g_Bf.
// ---------------------------------------------------------------------------
__global__ void bspline_prep_kernel(const float* __restrict__ cp) {
    int tid = blockIdx.x * blockDim.x + threadIdx.x;
    if (tid < KSTEPS * 64 * 4) {
        int kq = tid & 3;
        int n = (tid >> 2) & 63;
        int kstep = tid >> 8;
        int k0 = kstep * 16 + kq * 2;
        uint2 v;
        v.x = packh2(cp[(k0 + 0) * 64 + n], cp[(k0 + 1) * 64 + n]);
        v.y = packh2(cp[(k0 + 8) * 64 + n], cp[(k0 + 9) * 64 + n]);
        g_Bf[tid] = v;
    }
}

// ---------------------------------------------------------------------------
// Main kernel: one CTA = 64 rows, 8 warps = 4(M) x 2(N), warp tile M16xN32.
// K processed in 4 passes of 192 (i in [16p, 16p+16), ksteps [12p, 12p+12)).
// ---------------------------------------------------------------------------
__global__ __launch_bounds__(THREADS, 4)
void bspline_hmma_kernel(const float* __restrict__ x,
                         float* __restrict__ out,
                         int nrows)
{
    extern __shared__ char sm[];
    const uint32_t sb = s2u(sm);
    const int t = threadIdx.x;
    const int wid = t >> 5;
    const int lid = t & 31;
    const int row0 = blockIdx.x * M_TILE;

    // Per-span table: {T[j-2..j+3], i1,i2a,i2b,i3a,i3b,i3c}, j = s+3
    float* tab = (float*)(sm + SMEM_TAB);
    if (t < 9) {
        const int j = t + 3;
        float* e = tab + t * 12;
        e[0] = knotv(j - 2); e[1] = knotv(j - 1); e[2] = knotv(j);
        e[3] = knotv(j + 1); e[4] = knotv(j + 2); e[5] = knotv(j + 3);
        e[6]  = 1.0f / (e[3] - e[2]);
        e[7]  = 1.0f / (e[3] - e[1]);
        e[8]  = 1.0f / (e[4] - e[2]);
        e[9]  = 1.0f / (e[3] - e[0]);
        e[10] = 1.0f / (e[4] - e[1]);
        e[11] = 1.0f / (e[5] - e[2]);
    }

    // ---------------- Stage x tile: fully coalesced, once ----------------
    // 64 rows x 16 quads = 1024 float4, 4 per thread, contiguous in global.
    #pragma unroll
    for (int s = 0; s < 4; s++) {
        const int f = s * THREADS + t;
        const int r = f >> 4;
        const int q = f & 15;
        float4 v = make_float4(0.f, 0.f, 0.f, 0.f);
        if (row0 + r < nrows)
            v = ldg_cs_f4(x + (size_t)row0 * DIMS + f * 4);
        *(float4*)(sm + SMEM_XS + r * XS_PITCH_B + q * 16) = v;
    }

    // Warp-tile constants (stable across passes)
    const int mbase = (wid >> 1) * 16;      // 0,16,32,48
    const int nb    = wid & 1;              // N group -> nbase = nb*32
    const int lrow = (lid & 7) + ((lid >> 3) & 1) * 8;
    const int lcol = (lid >> 4) * 16;
    const uint32_t aAddr = sb + SMEM_A + (uint32_t)(mbase + lrow) * A_PITCH_B + lcol;
    const uint2* __restrict__ Bf = g_Bf;
    const int bLane = (nb * 32 + (lid >> 2)) * 4 + (lid & 3);

    float acc[4][4];
    #pragma unroll
    for (int nt = 0; nt < 4; nt++)
        #pragma unroll
        for (int q = 0; q < 4; q++) acc[nt][q] = 0.0f;

    #pragma unroll
    for (int pass = 0; pass < NPASS; pass++) {
        __syncthreads();   // pass 0: x/tab staged; later: A-tile WAR

        // ------------- Build phase: i in [16*pass, 16*pass+16) -------------
        // 64 rows x 4 i-quads = 256 tasks, 1 per thread; x from SMEM.
        {
            const int r = t >> 2;               // row in tile
            const int iql = t & 3;              // local i-quad (0..3)

            const float4 xv = *(const float4*)(
                sm + SMEM_XS + r * XS_PITCH_B + (pass * 4 + iql) * 16);
            const uint32_t wbase = sb + SMEM_A
                                 + (uint32_t)r * A_PITCH_B + (uint32_t)iql * 96u;

            #pragma unroll
            for (int u = 0; u < 4; u++) {
                float xc = (u == 0) ? xv.x : (u == 1) ? xv.y : (u == 2) ? xv.z : xv.w;
                xc = fminf(fmaxf(xc, 0.0f), 1.0f);

                const int s9 = min(8, (int)(xc * 9.0f));
                const float4* tb = (const float4*)(tab + s9 * 12);
                const float4 t0 = tb[0];
                const float4 t1 = tb[1];
                const float4 t2 = tb[2];

                const float l1 = xc - t0.z, r1 = t0.w - xc;
                const float l2 = xc - t0.y, r2 = t1.x - xc;
                const float l3 = xc - t0.x, r3 = t1.y - xc;

                float N0, N1, N2, N3, tmp, sv;
                tmp = t1.z;
                N0 = r1 * tmp; N1 = l1 * tmp;
                tmp = N0 * t1.w;
                N0 = r1 * tmp; sv = l2 * tmp;
                tmp = N1 * t2.x;
                N1 = fmaf(r2, tmp, sv); N2 = l1 * tmp;
                tmp = N0 * t2.y;
                N0 = r1 * tmp; sv = l3 * tmp;
                tmp = N1 * t2.z;
                N1 = fmaf(r2, tmp, sv); sv = l2 * tmp;
                tmp = N2 * t2.w;
                N2 = fmaf(r3, tmp, sv); N3 = l1 * tmp;

                const uint64_t w64 = (uint64_t)packh2(N0, N1)
                                   | ((uint64_t)packh2(N2, N3) << 32);
                const int sl = s9 >> 2;
                const int rs = (s9 & 3) * 16;
                const uint64_t lo = w64 << rs;
                const uint64_t hi = rs ? (w64 >> (64 - rs)) : 0ULL;

                const uint64_t a0 = (sl == 0) ? lo : 0ULL;
                const uint64_t a1 = (sl == 1) ? lo : ((sl == 0) ? hi : 0ULL);
                const uint64_t a2 = (sl == 2) ? lo : ((sl == 1) ? hi : 0ULL);

                const uint32_t w = wbase + (uint32_t)u * 24u;
                asm volatile("st.shared.u64 [%0], %1;" :: "r"(w),      "l"(a0) : "memory");
                asm volatile("st.shared.u64 [%0], %1;" :: "r"(w + 8),  "l"(a1) : "memory");
                asm volatile("st.shared.u64 [%0], %1;" :: "r"(w + 16), "l"(a2) : "memory");
            }
        }
        __syncthreads();

        // ------------- MMA phase: ksteps [12*pass, 12*pass+12) -------------
        uint32_t a[2][4];
        uint2 b[2][4];

        const int ksg0 = pass * KS_PASS;
        ldsm_x4(a[0][0], a[0][1], a[0][2], a[0][3], aAddr);
        {
            const int bi = ksg0 * 256 + bLane;
            #pragma unroll
            for (int nt = 0; nt < 4; nt++) b[0][nt] = __ldg(Bf + bi + nt * 32);
        }

        #pragma unroll 4
        for (int ksl = 0; ksl < KS_PASS; ksl++) {
            const int cur = ksl & 1;
            const int nxt = cur ^ 1;
            if (ksl + 1 < KS_PASS) {
                ldsm_x4(a[nxt][0], a[nxt][1], a[nxt][2], a[nxt][3],
                        aAddr + (ksl + 1) * 32);
                const int bi = (ksg0 + ksl + 1) * 256 + bLane;
                #pragma unroll
                for (int nt = 0; nt < 4; nt++) b[nxt][nt] = __ldg(Bf + bi + nt * 32);
            }
            #pragma unroll
            for (int nt = 0; nt < 4; nt++)
                mma16816(acc[nt][0], acc[nt][1], acc[nt][2], acc[nt][3],
                         a[cur][0], a[cur][1], a[cur][2], a[cur][3],
                         b[cur][nt].x, b[cur][nt].y);
        }
    }

    // ---------------- Epilogue: restage via SMEM, coalesced stores --------
    // x tile region is dead after the last build phase; reuse it for D.
    __syncthreads();
    {
        const int rquad = lid >> 2;
        const int npair = (lid & 3) * 2;
        #pragma unroll
        for (int nt = 0; nt < 4; nt++) {
            const int col = nb * 32 + nt * 8 + npair;
            const uint32_t aA = sb + SMEM_XS
                              + (uint32_t)(mbase + rquad) * XS_PITCH_B + col * 4;
            asm volatile("st.shared.v2.f32 [%0], {%1,%2};"
                         :: "r"(aA), "f"(acc[nt][0]), "f"(acc[nt][1]) : "memory");
            asm volatile("st.shared.v2.f32 [%0], {%1,%2};"
                         :: "r"(aA + 8u * XS_PITCH_B), "f"(acc[nt][2]), "f"(acc[nt][3]) : "memory");
        }
    }
    __syncthreads();

    #pragma unroll
    for (int s = 0; s < 4; s++) {
        const int f = s * THREADS + t;
        const int r = f >> 4;
        const int q = f & 15;
        if (row0 + r < nrows) {
            float4 v = *(const float4*)(sm + SMEM_XS + r * XS_PITCH_B + q * 16);
            stg_cs_f4(out + (size_t)row0 * DIMS + f * 4, v);
        }
    }
}

extern "C" void kernel_launch(void* const* d_in, const int* in_sizes, int n_in,
                              void* d_out, int out_size)
{
    const float* x  = (const float*)d_in[0];   // (65536, 64)
    const float* cp = (const float*)d_in[1];   // (64, 12, 64) == B[768][64]
    float* out = (float*)d_out;

    const int nrows = in_sizes[0] / DIMS;

    bspline_prep_kernel<<<(KSTEPS * 64 * 4 + 255) / 256, 256>>>(cp);

    cudaFuncSetAttribute(bspline_hmma_kernel,
                         cudaFuncAttributeMaxDynamicSharedMemorySize, SMEM_TOTAL);
    const int grid = (nrows + M_TILE - 1) / M_TILE;
    bspline_hmma_kernel<<<grid, THREADS, SMEM_TOTAL>>>(x, out, nrows);
}

// round 15
// speedup vs baseline: 1.3174x; 1.1144x over previous
#include <cuda_runtime.h>
#include <cuda_fp16.h>
#include <cstdint>

// ============================================================================
// BSpline via warp-level mma.sync (HMMA).
//   out[b,o] = sum_{i,c} basis(x[b,i])[c] * cp[i,c,o]
//   = GEMM: A (rows x 768) * B (768 x 64), k = i*12 + c.
// R15 = R12 (best, 41.5us: M16xN32, 4 k-passes, 4 CTA/SM, 32 warps/SM) +
//   (1) arithmetic knots/reciprocals (clamped-uniform: T=clamp(s±d,0,9)/9,
//       inverses in {9,4.5,3} by compare) — removes the per-window divergent
//       LDS.128 table gathers (~25% of L1 wavefronts) and the table itself;
//   (2) corrected SoA B repack: 2 dense LDG.128 per kstep (same wavefronts,
//       half the LDG instructions; R7's version had a 32B-stride layout bug).
// ============================================================================

#define DIMS 64
#define KSTEPS 48          // 768 / 16
#define NPASS 4
#define KS_PASS 12         // ksteps per pass
#define M_TILE 64
#define THREADS 256

#define A_PITCH_B 400      // bytes per A row per pass (odd x 16B)
#define SMEM_TOTAL (M_TILE * A_PITCH_B + 16)     // 25616

// B fragments, SoA lane-contiguous uint4:
//   g_Bf3[ ((ks*2 + nb)*2 + q)*32 + lane ] =
//     { frag(nt=2q).lo, frag(nt=2q).hi, frag(nt=2q+1).lo, frag(nt=2q+1).hi }
//   frag(nt) for lane: n = nb*32 + nt*8 + (lane>>2), kq = lane&3,
//     lo = h2(cp[k0][n],cp[k0+1][n]), hi = h2(cp[k0+8][n],cp[k0+9][n]),
//     k0 = ks*16 + kq*2.
__device__ uint4 g_Bf3[KSTEPS * 2 * 2 * 32];

static __device__ __forceinline__ uint32_t s2u(const void* p) {
    uint32_t a;
    asm("{ .reg .u64 t; cvta.to.shared.u64 t, %1; cvt.u32.u64 %0, t; }" : "=r"(a) : "l"(p));
    return a;
}

static __device__ __forceinline__ float4 ldg_cs_f4(const float* p) {
    float4 v;
    asm volatile("ld.global.cs.v4.f32 {%0,%1,%2,%3}, [%4];"
                 : "=f"(v.x), "=f"(v.y), "=f"(v.z), "=f"(v.w) : "l"(p));
    return v;
}

static __device__ __forceinline__ void stg_cs_f2(float* p, float a, float b) {
    asm volatile("st.global.cs.v2.f32 [%0], {%1,%2};" :: "l"(p), "f"(a), "f"(b) : "memory");
}

static __device__ __forceinline__ void ldsm_x4(uint32_t& r0, uint32_t& r1,
                                               uint32_t& r2, uint32_t& r3,
                                               uint32_t addr) {
    asm volatile("ldmatrix.sync.aligned.m8n8.x4.shared.b16 {%0,%1,%2,%3}, [%4];"
                 : "=r"(r0), "=r"(r1), "=r"(r2), "=r"(r3) : "r"(addr));
}

static __device__ __forceinline__ void mma16816(float& d0, float& d1, float& d2, float& d3,
                                                uint32_t a0, uint32_t a1, uint32_t a2, uint32_t a3,
                                                uint32_t b0, uint32_t b1) {
    asm("mma.sync.aligned.m16n8k16.row.col.f32.f16.f16.f32 "
        "{%0,%1,%2,%3}, {%4,%5,%6,%7}, {%8,%9}, {%0,%1,%2,%3};"
        : "+f"(d0), "+f"(d1), "+f"(d2), "+f"(d3)
        : "r"(a0), "r"(a1), "r"(a2), "r"(a3), "r"(b0), "r"(b1));
}

static __device__ __forceinline__ uint32_t packh2(float a, float b) {
    uint32_t r;
    asm("cvt.rn.f16x2.f32 %0, %2, %1;" : "=r"(r) : "f"(a), "f"(b));
    return r;
}

// ---------------------------------------------------------------------------
// Prep: cp fp32 (seen as [k][o], k = i*12+c) -> SoA fragment-ordered fp16.
// ---------------------------------------------------------------------------
__global__ void bspline_prep_kernel(const float* __restrict__ cp) {
    int tid = blockIdx.x * blockDim.x + threadIdx.x;
    if (tid < KSTEPS * 2 * 2 * 32) {
        int lane = tid & 31;
        int q  = (tid >> 5) & 1;
        int nb = (tid >> 6) & 1;
        int ks = tid >> 7;
        int kq = lane & 3;
        int k0 = ks * 16 + kq * 2;
        int nbase = nb * 32 + (lane >> 2);
        int nA = nbase + (2 * q) * 8;
        int nB = nbase + (2 * q + 1) * 8;
        uint4 v;
        v.x = packh2(cp[(k0 + 0) * 64 + nA], cp[(k0 + 1) * 64 + nA]);
        v.y = packh2(cp[(k0 + 8) * 64 + nA], cp[(k0 + 9) * 64 + nA]);
        v.z = packh2(cp[(k0 + 0) * 64 + nB], cp[(k0 + 1) * 64 + nB]);
        v.w = packh2(cp[(k0 + 8) * 64 + nB], cp[(k0 + 9) * 64 + nB]);
        g_Bf3[tid] = v;
    }
}

// ---------------------------------------------------------------------------
// Main kernel: one CTA = 64 rows, 8 warps = 4(M) x 2(N), warp tile M16xN32.
// K processed in 4 passes of 192 (i in [16p, 16p+16), ksteps [12p, 12p+12)).
// ---------------------------------------------------------------------------
__global__ __launch_bounds__(THREADS, 4)
void bspline_hmma_kernel(const float* __restrict__ x,
                         float* __restrict__ out,
                         int nrows)
{
    extern __shared__ char sm[];
    const uint32_t sb = s2u(sm);
    const int t = threadIdx.x;
    const int wid = t >> 5;
    const int lid = t & 31;
    const int row0 = blockIdx.x * M_TILE;

    // Warp-tile constants (stable across passes)
    const int mbase = (wid >> 1) * 16;      // 0,16,32,48
    const int nb    = wid & 1;              // N group -> nbase = nb*32
    const int lrow = (lid & 7) + ((lid >> 3) & 1) * 8;
    const int lcol = (lid >> 4) * 16;
    const uint32_t aAddr = sb + (uint32_t)(mbase + lrow) * A_PITCH_B + lcol;
    const uint4* __restrict__ Bf = g_Bf3 + (size_t)(nb * 64 + lid);

    float acc[4][4];
    #pragma unroll
    for (int nt = 0; nt < 4; nt++)
        #pragma unroll
        for (int q = 0; q < 4; q++) acc[nt][q] = 0.0f;

    #pragma unroll
    for (int pass = 0; pass < NPASS; pass++) {
        __syncthreads();   // A-tile WAR between passes (no-op cost on pass 0)

        // ------------- Build phase: i in [16*pass, 16*pass+16) -------------
        // 64 rows x 4 i-quads = 256 tasks, 1 per thread.
        {
            const int r = t >> 2;               // row in tile
            const int iql = t & 3;              // local i-quad (0..3)
            const int row = min(row0 + r, nrows - 1);

            const float4 xv = ldg_cs_f4(x + (size_t)row * DIMS + (pass * 4 + iql) * 4);
            const uint32_t wbase = sb + (uint32_t)r * A_PITCH_B + (uint32_t)iql * 96u;

            #pragma unroll
            for (int u = 0; u < 4; u++) {
                float xc = (u == 0) ? xv.x : (u == 1) ? xv.y : (u == 2) ? xv.z : xv.w;
                xc = fminf(fmaxf(xc, 0.0f), 1.0f);

                const int s9 = min(8, (int)(xc * 9.0f));
                const float sf = (float)s9;
                const float C9 = 1.0f / 9.0f;

                // Clamped-uniform knots: T[j+d] = clamp(s9+d, 0, 9) / 9
                const float Tj   = sf * C9;
                const float Tjp1 = (sf + 1.0f) * C9;
                const float Tjm1 = fmaxf(sf - 1.0f, 0.0f) * C9;
                const float Tjm2 = fmaxf(sf - 2.0f, 0.0f) * C9;
                const float Tjp2 = fminf(sf + 2.0f, 9.0f) * C9;
                const float Tjp3 = fminf(sf + 3.0f, 9.0f) * C9;

                const float l1 = xc - Tj,   r1 = Tjp1 - xc;
                const float l2 = xc - Tjm1, r2 = Tjp2 - xc;
                const float l3 = xc - Tjm2, r3 = Tjp3 - xc;

                // Reciprocal knot spans: only {9, 4.5, 3} occur.
                const float i2a = (s9 == 0) ? 9.0f : 4.5f;
                const float i2b = (s9 == 8) ? 9.0f : 4.5f;
                const float i3a = (s9 >= 2) ? 3.0f : ((s9 == 1) ? 4.5f : 9.0f);
                const float i3b = (s9 == 0 || s9 == 8) ? 4.5f : 3.0f;
                const float i3c = (s9 <= 6) ? 3.0f : ((s9 == 7) ? 4.5f : 9.0f);

                float N0, N1, N2, N3, tmp, sv;
                N0 = r1 * 9.0f; N1 = l1 * 9.0f;           // level 1 (i1 = 9)
                tmp = N0 * i2a;
                N0 = r1 * tmp; sv = l2 * tmp;
                tmp = N1 * i2b;
                N1 = fmaf(r2, tmp, sv); N2 = l1 * tmp;
                tmp = N0 * i3a;
                N0 = r1 * tmp; sv = l3 * tmp;
                tmp = N1 * i3b;
                N1 = fmaf(r2, tmp, sv); sv = l2 * tmp;
                tmp = N2 * i3c;
                N2 = fmaf(r3, tmp, sv); N3 = l1 * tmp;

                const uint64_t w64 = (uint64_t)packh2(N0, N1)
                                   | ((uint64_t)packh2(N2, N3) << 32);
                const int sl = s9 >> 2;
                const int rs = (s9 & 3) * 16;
                const uint64_t lo = w64 << rs;
                const uint64_t hi = rs ? (w64 >> (64 - rs)) : 0ULL;

                const uint64_t a0 = (sl == 0) ? lo : 0ULL;
                const uint64_t a1 = (sl == 1) ? lo : ((sl == 0) ? hi : 0ULL);
                const uint64_t a2 = (sl == 2) ? lo : ((sl == 1) ? hi : 0ULL);

                const uint32_t w = wbase + (uint32_t)u * 24u;
                asm volatile("st.shared.u64 [%0], %1;" :: "r"(w),      "l"(a0) : "memory");
                asm volatile("st.shared.u64 [%0], %1;" :: "r"(w + 8),  "l"(a1) : "memory");
                asm volatile("st.shared.u64 [%0], %1;" :: "r"(w + 16), "l"(a2) : "memory");
            }
        }
        __syncthreads();

        // ------------- MMA phase: ksteps [12*pass, 12*pass+12) -------------
        uint32_t a[2][4];
        uint4 bb[2][2];

        const int ksg0 = pass * KS_PASS;
        ldsm_x4(a[0][0], a[0][1], a[0][2], a[0][3], aAddr);
        bb[0][0] = __ldg(Bf + ksg0 * 128);
        bb[0][1] = __ldg(Bf + ksg0 * 128 + 32);

        #pragma unroll 4
        for (int ksl = 0; ksl < KS_PASS; ksl++) {
            const int cur = ksl & 1;
            const int nxt = cur ^ 1;
            if (ksl + 1 < KS_PASS) {
                ldsm_x4(a[nxt][0], a[nxt][1], a[nxt][2], a[nxt][3],
                        aAddr + (ksl + 1) * 32);
                const int bi = (ksg0 + ksl + 1) * 128;
                bb[nxt][0] = __ldg(Bf + bi);
                bb[nxt][1] = __ldg(Bf + bi + 32);
            }
            const uint32_t b0[4] = { bb[cur][0].x, bb[cur][0].z, bb[cur][1].x, bb[cur][1].z };
            const uint32_t b1[4] = { bb[cur][0].y, bb[cur][0].w, bb[cur][1].y, bb[cur][1].w };
            #pragma unroll
            for (int nt = 0; nt < 4; nt++)
                mma16816(acc[nt][0], acc[nt][1], acc[nt][2], acc[nt][3],
                         a[cur][0], a[cur][1], a[cur][2], a[cur][3],
                         b0[nt], b1[nt]);
        }
    }

    // ---------------- Epilogue: streaming float2 stores ----------------
    const int rquad = lid >> 2;
    const int npair = (lid & 3) * 2;
    #pragma unroll
    for (int nt = 0; nt < 4; nt++) {
        const int col = nb * 32 + nt * 8 + npair;
        const int rA = row0 + mbase + rquad;
        const int rB = rA + 8;
        if (rA < nrows)
            stg_cs_f2(out + (size_t)rA * DIMS + col, acc[nt][0], acc[nt][1]);
        if (rB < nrows)
            stg_cs_f2(out + (size_t)rB * DIMS + col, acc[nt][2], acc[nt][3]);
    }
}

extern "C" void kernel_launch(void* const* d_in, const int* in_sizes, int n_in,
                              void* d_out, int out_size)
{
    const float* x  = (const float*)d_in[0];   // (65536, 64)
    const float* cp = (const float*)d_in[1];   // (64, 12, 64) == B[768][64]
    float* out = (float*)d_out;

    const int nrows = in_sizes[0] / DIMS;

    bspline_prep_kernel<<<(KSTEPS * 2 * 2 * 32 + 255) / 256, 256>>>(cp);

    cudaFuncSetAttribute(bspline_hmma_kernel,
                         cudaFuncAttributeMaxDynamicSharedMemorySize, SMEM_TOTAL);
    const int grid = (nrows + M_TILE - 1) / M_TILE;
    bspline_hmma_kernel<<<grid, THREADS, SMEM_TOTAL>>>(x, out, nrows);
}